// round 5
// baseline (speedup 1.0000x reference)
#include <cuda_runtime.h>
#include <cuda_bf16.h>
#include <cstdint>

// ============================================================================
// MambaBlock, bf16x3 HMMA with pre-converted hi/lo operands + cp.async.
//   uv = x@Wi^T+bi ; y = silu(dwconv3(v))*u ; out = y@Wo^T+bo
// ============================================================================

#define MROWS 16384
#define DDIM  1024
#define LSEQ  4096

#define BM 128
#define BN 128
#define BK 32
#define SP 40                    // SMEM row stride in bf16 (32 + 8 pad); 80B = 5*16
#define NTH 256

#define A_HI 0
#define A_LO (BM * SP * 2)       // 10240
#define B_HI (2 * BM * SP * 2)   // 20480
#define B_LO (3 * BM * SP * 2)   // 30720
#define STAGE_BYTES (4 * BM * SP * 2)   // 40960
#define SMEMSZ (2 * STAGE_BYTES)        // 81920

// fp32 scratch for uv; bf16 hi/lo operand buffers
__device__ float g_uv[(size_t)MROWS * 2 * DDIM];
__device__ __nv_bfloat16 g_xhi[(size_t)MROWS * DDIM];
__device__ __nv_bfloat16 g_xlo[(size_t)MROWS * DDIM];
__device__ __nv_bfloat16 g_yhi[(size_t)MROWS * DDIM];
__device__ __nv_bfloat16 g_ylo[(size_t)MROWS * DDIM];
__device__ __nv_bfloat16 g_wihi[(size_t)2 * DDIM * DDIM];
__device__ __nv_bfloat16 g_wilo[(size_t)2 * DDIM * DDIM];
__device__ __nv_bfloat16 g_wohi[(size_t)DDIM * DDIM];
__device__ __nv_bfloat16 g_wolo[(size_t)DDIM * DDIM];

__device__ __forceinline__ void mma_bf16(float* c, const uint32_t* a,
                                         uint32_t b0, uint32_t b1) {
    asm volatile(
        "mma.sync.aligned.m16n8k16.row.col.f32.bf16.bf16.f32 "
        "{%0,%1,%2,%3}, {%4,%5,%6,%7}, {%8,%9}, {%0,%1,%2,%3};"
        : "+f"(c[0]), "+f"(c[1]), "+f"(c[2]), "+f"(c[3])
        : "r"(a[0]), "r"(a[1]), "r"(a[2]), "r"(a[3]), "r"(b0), "r"(b1));
}

#define LDSM4(r0, r1, r2, r3, addr)                                        \
    asm volatile("ldmatrix.sync.aligned.m8n8.x4.shared.b16 {%0,%1,%2,%3}, [%4];" \
                 : "=r"(r0), "=r"(r1), "=r"(r2), "=r"(r3) : "r"(addr))

#define CPA16(dst, src) \
    asm volatile("cp.async.cg.shared.global [%0], [%1], 16;" :: "r"(dst), "l"(src))
#define CP_COMMIT() asm volatile("cp.async.commit_group;" ::: "memory")
#define CP_WAIT1()  asm volatile("cp.async.wait_group 1;" ::: "memory")
#define CP_WAIT0()  asm volatile("cp.async.wait_group 0;" ::: "memory")

__device__ __forceinline__ void cvt_hilo4(float4 v, uint32_t& h0, uint32_t& h1,
                                          uint32_t& l0, uint32_t& l1) {
    __nv_bfloat162 H0 = __floats2bfloat162_rn(v.x, v.y);
    __nv_bfloat162 H1 = __floats2bfloat162_rn(v.z, v.w);
    float r0 = v.x - __bfloat162float(H0.x);
    float r1 = v.y - __bfloat162float(H0.y);
    float r2 = v.z - __bfloat162float(H1.x);
    float r3 = v.w - __bfloat162float(H1.y);
    __nv_bfloat162 L0 = __floats2bfloat162_rn(r0, r1);
    __nv_bfloat162 L1 = __floats2bfloat162_rn(r2, r3);
    h0 = *reinterpret_cast<uint32_t*>(&H0);
    h1 = *reinterpret_cast<uint32_t*>(&H1);
    l0 = *reinterpret_cast<uint32_t*>(&L0);
    l1 = *reinterpret_cast<uint32_t*>(&L1);
}

// elementwise fp32 -> bf16 hi/lo (4 elems/thread)
__global__ __launch_bounds__(256)
void cvt_kernel(const float* __restrict__ src, __nv_bfloat16* __restrict__ hi,
                __nv_bfloat16* __restrict__ lo) {
    size_t i4 = ((size_t)blockIdx.x * 256 + threadIdx.x) * 4;
    float4 v = *(const float4*)(src + i4);
    uint32_t h0, h1, l0, l1;
    cvt_hilo4(v, h0, h1, l0, l1);
    *(uint2*)((char*)hi + i4 * 2) = make_uint2(h0, h1);
    *(uint2*)((char*)lo + i4 * 2) = make_uint2(l0, l1);
}

// ---------------------------------------------------------------------------
// C[M,N] = (Ahi+Alo)[M,K] @ (Bhi+Blo)[N,K]^T + bias (lo*lo dropped)
// ---------------------------------------------------------------------------
template <int N, int K>
__global__ __launch_bounds__(NTH, 2)
void gemm_mma(const __nv_bfloat16* __restrict__ Ahi, const __nv_bfloat16* __restrict__ Alo,
              const __nv_bfloat16* __restrict__ Bhi, const __nv_bfloat16* __restrict__ Blo,
              const float* __restrict__ bias, float* __restrict__ C) {
    extern __shared__ __align__(16) char sm[];
    const uint32_t smb = (uint32_t)__cvta_generic_to_shared(sm);
    const int tid  = threadIdx.x;
    const int lane = tid & 31;
    const int wid  = tid >> 5;
    const int wm   = wid & 3;
    const int wn   = wid >> 2;
    const int qr   = lane >> 2;
    const int qc   = (lane & 3) * 2;
    const int row0 = blockIdx.y * BM;
    const int col0 = blockIdx.x * BN;

    const int m8 = lane >> 3;
    const int rr = lane & 7;
    const uint32_t aLane = (uint32_t)(((wm * 32 + (m8 & 1) * 8 + rr) * SP + (m8 >> 1) * 8) * 2);
    const uint32_t bLane = (uint32_t)(((wn * 64 + (m8 >> 1) * 8 + rr) * SP + (m8 & 1) * 8) * 2);

    // loader: 512 16B-chunks per buffer; thread covers 2 (id, id+256)
    const int l_r0 = tid >> 2;       // rows 0..63, +64 for rep 1
    const int l_c  = (tid & 3) * 16; // byte col within 64B row

    float acc[2][8][4];
#pragma unroll
    for (int i = 0; i < 2; i++)
#pragma unroll
        for (int j = 0; j < 8; j++)
#pragma unroll
            for (int k = 0; k < 4; k++) acc[i][j][k] = 0.f;

    const char* pAh = (const char*)(Ahi + (size_t)row0 * K);
    const char* pAl = (const char*)(Alo + (size_t)row0 * K);
    const char* pBh = (const char*)(Bhi + (size_t)col0 * K);
    const char* pBl = (const char*)(Blo + (size_t)col0 * K);

#define LOAD_STAGE(stageOff, kt) do {                                          \
    const uint32_t so_ = smb + (stageOff);                                     \
    const size_t kb_ = (size_t)(kt) * 2;                                       \
    _Pragma("unroll")                                                          \
    for (int rep = 0; rep < 2; rep++) {                                        \
        int r = l_r0 + rep * 64;                                               \
        uint32_t d = so_ + (uint32_t)(r * (SP * 2) + l_c);                     \
        size_t g = (size_t)r * (K * 2) + kb_ + l_c;                            \
        CPA16(d + A_HI, pAh + g);                                              \
        CPA16(d + A_LO, pAl + g);                                              \
        CPA16(d + B_HI, pBh + g);                                              \
        CPA16(d + B_LO, pBl + g);                                              \
    }                                                                          \
} while (0)

    // prologue
    LOAD_STAGE(0, 0);
    CP_COMMIT();

    constexpr int NCH = K / BK;
#pragma unroll 1
    for (int ck = 0; ck < NCH; ck++) {
        if (ck + 1 < NCH) {
            LOAD_STAGE((uint32_t)(((ck + 1) & 1) * STAGE_BYTES), (ck + 1) * BK);
            CP_COMMIT();
            CP_WAIT1();
        } else {
            CP_WAIT0();
        }
        __syncthreads();

        const uint32_t sto = smb + (uint32_t)((ck & 1) * STAGE_BYTES);
#pragma unroll
        for (int kb = 0; kb < BK; kb += 16) {
            uint32_t ah[2][4], al[2][4];
#pragma unroll
            for (int mt = 0; mt < 2; mt++) {
                uint32_t ao = sto + aLane + (uint32_t)((mt * 16 * SP + kb) * 2);
                LDSM4(ah[mt][0], ah[mt][1], ah[mt][2], ah[mt][3], ao + A_HI);
                LDSM4(al[mt][0], al[mt][1], al[mt][2], al[mt][3], ao + A_LO);
            }
#pragma unroll
            for (int ntp = 0; ntp < 4; ntp++) {
                uint32_t bo = sto + bLane + (uint32_t)((ntp * 16 * SP + kb) * 2);
                uint32_t bh0, bh1, bh2, bh3, bl0, bl1, bl2, bl3;
                LDSM4(bh0, bh1, bh2, bh3, bo + B_HI);
                LDSM4(bl0, bl1, bl2, bl3, bo + B_LO);
#pragma unroll
                for (int mt = 0; mt < 2; mt++) {
                    float* c0 = acc[mt][2 * ntp];
                    float* c1 = acc[mt][2 * ntp + 1];
                    mma_bf16(c0, ah[mt], bh0, bh1);
                    mma_bf16(c1, ah[mt], bh2, bh3);
                    mma_bf16(c0, al[mt], bh0, bh1);
                    mma_bf16(c1, al[mt], bh2, bh3);
                    mma_bf16(c0, ah[mt], bl0, bl1);
                    mma_bf16(c1, ah[mt], bl2, bl3);
                }
            }
        }
        __syncthreads();
    }
#undef LOAD_STAGE

    // epilogue: bias + store
#pragma unroll
    for (int mt = 0; mt < 2; mt++) {
        int row = row0 + wm * 32 + mt * 16 + qr;
#pragma unroll
        for (int nt = 0; nt < 8; nt++) {
            int col = col0 + wn * 64 + nt * 8 + qc;
            float b0 = __ldg(&bias[col]);
            float b1 = __ldg(&bias[col + 1]);
            float2 o0 = make_float2(acc[mt][nt][0] + b0, acc[mt][nt][1] + b1);
            float2 o1 = make_float2(acc[mt][nt][2] + b0, acc[mt][nt][3] + b1);
            *(float2*)(C + (size_t)row * N + col) = o0;
            *(float2*)(C + (size_t)(row + 8) * N + col) = o1;
        }
    }
}

// ---------------------------------------------------------------------------
// depthwise conv3 + silu gate; emits y as bf16 hi/lo
// ---------------------------------------------------------------------------
__global__ __launch_bounds__(256)
void conv_gate_kernel(const float* __restrict__ Wc, const float* __restrict__ bc) {
    int idx = blockIdx.x * blockDim.x + threadIdx.x;
    int m = idx >> 8;
    int d = (idx & 255) << 2;
    int l = m & (LSEQ - 1);

    const float* urow = g_uv + (size_t)m * (2 * DDIM);
    const float* vrow = urow + DDIM;

    float4 vc = *(const float4*)(vrow + d);
    float4 vp = make_float4(0.f, 0.f, 0.f, 0.f);
    float4 vn = make_float4(0.f, 0.f, 0.f, 0.f);
    if (l > 0)        vp = *(const float4*)(vrow - 2 * DDIM + d);
    if (l < LSEQ - 1) vn = *(const float4*)(vrow + 2 * DDIM + d);
    float4 uu = *(const float4*)(urow + d);

    float p[4] = {vp.x, vp.y, vp.z, vp.w};
    float c[4] = {vc.x, vc.y, vc.z, vc.w};
    float n[4] = {vn.x, vn.y, vn.z, vn.w};
    float u[4] = {uu.x, uu.y, uu.z, uu.w};
    float o[4];
#pragma unroll
    for (int j = 0; j < 4; j++) {
        int dd = d + j;
        float t = fmaf(p[j], Wc[dd * 3 + 0],
                  fmaf(c[j], Wc[dd * 3 + 1],
                  fmaf(n[j], Wc[dd * 3 + 2], bc[dd])));
        float s = 1.f / (1.f + __expf(-t));
        o[j] = t * s * u[j];
    }
    uint32_t h0, h1, l0, l1;
    cvt_hilo4(make_float4(o[0], o[1], o[2], o[3]), h0, h1, l0, l1);
    size_t off = ((size_t)m * DDIM + d) * 2;
    *(uint2*)((char*)g_yhi + off) = make_uint2(h0, h1);
    *(uint2*)((char*)g_ylo + off) = make_uint2(l0, l1);
}

// ---------------------------------------------------------------------------
extern "C" void kernel_launch(void* const* d_in, const int* in_sizes, int n_in,
                              void* d_out, int out_size) {
    const float* x  = (const float*)d_in[0];
    const float* Wi = (const float*)d_in[1];
    const float* bi = (const float*)d_in[2];
    const float* Wc = (const float*)d_in[3];
    const float* bc = (const float*)d_in[4];
    const float* Wo = (const float*)d_in[5];
    const float* bo = (const float*)d_in[6];
    float* out = (float*)d_out;

    float* uv_ptr;
    __nv_bfloat16 *xhi, *xlo, *yhi, *ylo, *wihi, *wilo, *wohi, *wolo;
    cudaGetSymbolAddress((void**)&uv_ptr, g_uv);
    cudaGetSymbolAddress((void**)&xhi, g_xhi);
    cudaGetSymbolAddress((void**)&xlo, g_xlo);
    cudaGetSymbolAddress((void**)&yhi, g_yhi);
    cudaGetSymbolAddress((void**)&ylo, g_ylo);
    cudaGetSymbolAddress((void**)&wihi, g_wihi);
    cudaGetSymbolAddress((void**)&wilo, g_wilo);
    cudaGetSymbolAddress((void**)&wohi, g_wohi);
    cudaGetSymbolAddress((void**)&wolo, g_wolo);

    cudaFuncSetAttribute(gemm_mma<2 * DDIM, DDIM>,
                         cudaFuncAttributeMaxDynamicSharedMemorySize, SMEMSZ);
    cudaFuncSetAttribute(gemm_mma<DDIM, DDIM>,
                         cudaFuncAttributeMaxDynamicSharedMemorySize, SMEMSZ);

    // pre-convert x, Wi, Wo to bf16 hi/lo
    cvt_kernel<<<(MROWS * DDIM) / 1024, 256>>>(x, xhi, xlo);
    cvt_kernel<<<(2 * DDIM * DDIM) / 1024, 256>>>(Wi, wihi, wilo);
    cvt_kernel<<<(DDIM * DDIM) / 1024, 256>>>(Wo, wohi, wolo);

    {   // GEMM1: uv = x @ Wi^T + bi
        dim3 grid(2 * DDIM / BN, MROWS / BM);
        gemm_mma<2 * DDIM, DDIM><<<grid, NTH, SMEMSZ>>>(xhi, xlo, wihi, wilo, bi, uv_ptr);
    }
    {   // conv + silu gate -> y hi/lo
        int total = MROWS * (DDIM / 4);
        conv_gate_kernel<<<total / 256, 256>>>(Wc, bc);
    }
    {   // GEMM2: out = y @ Wo^T + bo
        dim3 grid(DDIM / BN, MROWS / BM);
        gemm_mma<DDIM, DDIM><<<grid, NTH, SMEMSZ>>>(yhi, ylo, wohi, wolo, bo, out);
    }
}

// round 6
// speedup vs baseline: 1.0158x; 1.0158x over previous
#include <cuda_runtime.h>
#include <cuda_bf16.h>
#include <cstdint>

// ============================================================================
// MambaBlock, bf16x3 HMMA, pre-converted hi/lo operands, cp.async pipeline.
// R6: product-major MMA ordering to break accumulator RAW chains.
// ============================================================================

#define MROWS 16384
#define DDIM  1024
#define LSEQ  4096

#define BM 128
#define BN 128
#define BK 32
#define SP 40                    // SMEM row stride in bf16 (32 + 8 pad)
#define NTH 256

#define A_HI 0
#define A_LO (BM * SP * 2)
#define B_HI (2 * BM * SP * 2)
#define B_LO (3 * BM * SP * 2)
#define STAGE_BYTES (4 * BM * SP * 2)   // 40960
#define SMEMSZ (2 * STAGE_BYTES)        // 81920

__device__ float g_uv[(size_t)MROWS * 2 * DDIM];
__device__ __nv_bfloat16 g_xhi[(size_t)MROWS * DDIM];
__device__ __nv_bfloat16 g_xlo[(size_t)MROWS * DDIM];
__device__ __nv_bfloat16 g_yhi[(size_t)MROWS * DDIM];
__device__ __nv_bfloat16 g_ylo[(size_t)MROWS * DDIM];
__device__ __nv_bfloat16 g_wihi[(size_t)2 * DDIM * DDIM];
__device__ __nv_bfloat16 g_wilo[(size_t)2 * DDIM * DDIM];
__device__ __nv_bfloat16 g_wohi[(size_t)DDIM * DDIM];
__device__ __nv_bfloat16 g_wolo[(size_t)DDIM * DDIM];

__device__ __forceinline__ void mma_bf16(float* c, const uint32_t* a,
                                         uint32_t b0, uint32_t b1) {
    asm volatile(
        "mma.sync.aligned.m16n8k16.row.col.f32.bf16.bf16.f32 "
        "{%0,%1,%2,%3}, {%4,%5,%6,%7}, {%8,%9}, {%0,%1,%2,%3};"
        : "+f"(c[0]), "+f"(c[1]), "+f"(c[2]), "+f"(c[3])
        : "r"(a[0]), "r"(a[1]), "r"(a[2]), "r"(a[3]), "r"(b0), "r"(b1));
}

#define LDSM4(r0, r1, r2, r3, addr)                                        \
    asm volatile("ldmatrix.sync.aligned.m8n8.x4.shared.b16 {%0,%1,%2,%3}, [%4];" \
                 : "=r"(r0), "=r"(r1), "=r"(r2), "=r"(r3) : "r"(addr))

#define CPA16(dst, src) \
    asm volatile("cp.async.cg.shared.global [%0], [%1], 16;" :: "r"(dst), "l"(src))
#define CP_COMMIT() asm volatile("cp.async.commit_group;" ::: "memory")
#define CP_WAIT1()  asm volatile("cp.async.wait_group 1;" ::: "memory")
#define CP_WAIT0()  asm volatile("cp.async.wait_group 0;" ::: "memory")

__device__ __forceinline__ void cvt_hilo4(float4 v, uint32_t& h0, uint32_t& h1,
                                          uint32_t& l0, uint32_t& l1) {
    __nv_bfloat162 H0 = __floats2bfloat162_rn(v.x, v.y);
    __nv_bfloat162 H1 = __floats2bfloat162_rn(v.z, v.w);
    float r0 = v.x - __bfloat162float(H0.x);
    float r1 = v.y - __bfloat162float(H0.y);
    float r2 = v.z - __bfloat162float(H1.x);
    float r3 = v.w - __bfloat162float(H1.y);
    __nv_bfloat162 L0 = __floats2bfloat162_rn(r0, r1);
    __nv_bfloat162 L1 = __floats2bfloat162_rn(r2, r3);
    h0 = *reinterpret_cast<uint32_t*>(&H0);
    h1 = *reinterpret_cast<uint32_t*>(&H1);
    l0 = *reinterpret_cast<uint32_t*>(&L0);
    l1 = *reinterpret_cast<uint32_t*>(&L1);
}

__global__ __launch_bounds__(256)
void cvt_kernel(const float* __restrict__ src, __nv_bfloat16* __restrict__ hi,
                __nv_bfloat16* __restrict__ lo) {
    size_t i4 = ((size_t)blockIdx.x * 256 + threadIdx.x) * 4;
    float4 v = *(const float4*)(src + i4);
    uint32_t h0, h1, l0, l1;
    cvt_hilo4(v, h0, h1, l0, l1);
    *(uint2*)((char*)hi + i4 * 2) = make_uint2(h0, h1);
    *(uint2*)((char*)lo + i4 * 2) = make_uint2(l0, l1);
}

// ---------------------------------------------------------------------------
// C[M,N] = (Ahi+Alo)[M,K] @ (Bhi+Blo)[N,K]^T + bias (lo*lo dropped)
// ---------------------------------------------------------------------------
template <int N, int K>
__global__ __launch_bounds__(NTH, 2)
void gemm_mma(const __nv_bfloat16* __restrict__ Ahi, const __nv_bfloat16* __restrict__ Alo,
              const __nv_bfloat16* __restrict__ Bhi, const __nv_bfloat16* __restrict__ Blo,
              const float* __restrict__ bias, float* __restrict__ C) {
    extern __shared__ __align__(16) char sm[];
    const uint32_t smb = (uint32_t)__cvta_generic_to_shared(sm);
    const int tid  = threadIdx.x;
    const int lane = tid & 31;
    const int wid  = tid >> 5;
    const int wm   = wid & 3;
    const int wn   = wid >> 2;
    const int qr   = lane >> 2;
    const int qc   = (lane & 3) * 2;
    const int row0 = blockIdx.y * BM;
    const int col0 = blockIdx.x * BN;

    const int m8 = lane >> 3;
    const int rr = lane & 7;
    const uint32_t aLane = (uint32_t)(((wm * 32 + (m8 & 1) * 8 + rr) * SP + (m8 >> 1) * 8) * 2);
    const uint32_t bLane = (uint32_t)(((wn * 64 + (m8 >> 1) * 8 + rr) * SP + (m8 & 1) * 8) * 2);

    const int l_r0 = tid >> 2;
    const int l_c  = (tid & 3) * 16;

    float acc[2][8][4];
#pragma unroll
    for (int i = 0; i < 2; i++)
#pragma unroll
        for (int j = 0; j < 8; j++)
#pragma unroll
            for (int k = 0; k < 4; k++) acc[i][j][k] = 0.f;

    const char* pAh = (const char*)(Ahi + (size_t)row0 * K);
    const char* pAl = (const char*)(Alo + (size_t)row0 * K);
    const char* pBh = (const char*)(Bhi + (size_t)col0 * K);
    const char* pBl = (const char*)(Blo + (size_t)col0 * K);

#define LOAD_STAGE(stageOff, kt) do {                                          \
    const uint32_t so_ = smb + (stageOff);                                     \
    const size_t kb_ = (size_t)(kt) * 2;                                       \
    _Pragma("unroll")                                                          \
    for (int rep = 0; rep < 2; rep++) {                                        \
        int r = l_r0 + rep * 64;                                               \
        uint32_t d = so_ + (uint32_t)(r * (SP * 2) + l_c);                     \
        size_t g = (size_t)r * (K * 2) + kb_ + l_c;                            \
        CPA16(d + A_HI, pAh + g);                                              \
        CPA16(d + A_LO, pAl + g);                                              \
        CPA16(d + B_HI, pBh + g);                                              \
        CPA16(d + B_LO, pBl + g);                                              \
    }                                                                          \
} while (0)

    LOAD_STAGE(0, 0);
    CP_COMMIT();

    constexpr int NCH = K / BK;
#pragma unroll 1
    for (int ck = 0; ck < NCH; ck++) {
        if (ck + 1 < NCH) {
            LOAD_STAGE((uint32_t)(((ck + 1) & 1) * STAGE_BYTES), (ck + 1) * BK);
            CP_COMMIT();
            CP_WAIT1();
        } else {
            CP_WAIT0();
        }
        __syncthreads();

        const uint32_t sto = smb + (uint32_t)((ck & 1) * STAGE_BYTES);
#pragma unroll
        for (int kb = 0; kb < BK; kb += 16) {
            uint32_t ah[2][4], al[2][4], bh[4][4], bl[4][4];
#pragma unroll
            for (int mt = 0; mt < 2; mt++) {
                uint32_t ao = sto + aLane + (uint32_t)((mt * 16 * SP + kb) * 2);
                LDSM4(ah[mt][0], ah[mt][1], ah[mt][2], ah[mt][3], ao + A_HI);
                LDSM4(al[mt][0], al[mt][1], al[mt][2], al[mt][3], ao + A_LO);
            }
#pragma unroll
            for (int ntp = 0; ntp < 4; ntp++) {
                uint32_t bo = sto + bLane + (uint32_t)((ntp * 16 * SP + kb) * 2);
                LDSM4(bh[ntp][0], bh[ntp][1], bh[ntp][2], bh[ntp][3], bo + B_HI);
                LDSM4(bl[ntp][0], bl[ntp][1], bl[ntp][2], bl[ntp][3], bo + B_LO);
            }
            // pass 1: hi*hi  (16 independent accumulators)
#pragma unroll
            for (int mt = 0; mt < 2; mt++)
#pragma unroll
                for (int ntp = 0; ntp < 4; ntp++) {
                    mma_bf16(acc[mt][2 * ntp],     ah[mt], bh[ntp][0], bh[ntp][1]);
                    mma_bf16(acc[mt][2 * ntp + 1], ah[mt], bh[ntp][2], bh[ntp][3]);
                }
            // pass 2: lo*hi
#pragma unroll
            for (int mt = 0; mt < 2; mt++)
#pragma unroll
                for (int ntp = 0; ntp < 4; ntp++) {
                    mma_bf16(acc[mt][2 * ntp],     al[mt], bh[ntp][0], bh[ntp][1]);
                    mma_bf16(acc[mt][2 * ntp + 1], al[mt], bh[ntp][2], bh[ntp][3]);
                }
            // pass 3: hi*lo
#pragma unroll
            for (int mt = 0; mt < 2; mt++)
#pragma unroll
                for (int ntp = 0; ntp < 4; ntp++) {
                    mma_bf16(acc[mt][2 * ntp],     ah[mt], bl[ntp][0], bl[ntp][1]);
                    mma_bf16(acc[mt][2 * ntp + 1], ah[mt], bl[ntp][2], bl[ntp][3]);
                }
        }
        __syncthreads();
    }
#undef LOAD_STAGE

    // epilogue: bias + store
#pragma unroll
    for (int mt = 0; mt < 2; mt++) {
        int row = row0 + wm * 32 + mt * 16 + qr;
#pragma unroll
        for (int nt = 0; nt < 8; nt++) {
            int col = col0 + wn * 64 + nt * 8 + qc;
            float b0 = __ldg(&bias[col]);
            float b1 = __ldg(&bias[col + 1]);
            float2 o0 = make_float2(acc[mt][nt][0] + b0, acc[mt][nt][1] + b1);
            float2 o1 = make_float2(acc[mt][nt][2] + b0, acc[mt][nt][3] + b1);
            *(float2*)(C + (size_t)row * N + col) = o0;
            *(float2*)(C + (size_t)(row + 8) * N + col) = o1;
        }
    }
}

// ---------------------------------------------------------------------------
// depthwise conv3 + silu gate; emits y as bf16 hi/lo
// ---------------------------------------------------------------------------
__global__ __launch_bounds__(256)
void conv_gate_kernel(const float* __restrict__ Wc, const float* __restrict__ bc) {
    int idx = blockIdx.x * blockDim.x + threadIdx.x;
    int m = idx >> 8;
    int d = (idx & 255) << 2;
    int l = m & (LSEQ - 1);

    const float* urow = g_uv + (size_t)m * (2 * DDIM);
    const float* vrow = urow + DDIM;

    float4 vc = *(const float4*)(vrow + d);
    float4 vp = make_float4(0.f, 0.f, 0.f, 0.f);
    float4 vn = make_float4(0.f, 0.f, 0.f, 0.f);
    if (l > 0)        vp = *(const float4*)(vrow - 2 * DDIM + d);
    if (l < LSEQ - 1) vn = *(const float4*)(vrow + 2 * DDIM + d);
    float4 uu = *(const float4*)(urow + d);

    float p[4] = {vp.x, vp.y, vp.z, vp.w};
    float c[4] = {vc.x, vc.y, vc.z, vc.w};
    float n[4] = {vn.x, vn.y, vn.z, vn.w};
    float u[4] = {uu.x, uu.y, uu.z, uu.w};
    float o[4];
#pragma unroll
    for (int j = 0; j < 4; j++) {
        int dd = d + j;
        float t = fmaf(p[j], Wc[dd * 3 + 0],
                  fmaf(c[j], Wc[dd * 3 + 1],
                  fmaf(n[j], Wc[dd * 3 + 2], bc[dd])));
        float s = 1.f / (1.f + __expf(-t));
        o[j] = t * s * u[j];
    }
    uint32_t h0, h1, l0, l1;
    cvt_hilo4(make_float4(o[0], o[1], o[2], o[3]), h0, h1, l0, l1);
    size_t off = ((size_t)m * DDIM + d) * 2;
    *(uint2*)((char*)g_yhi + off) = make_uint2(h0, h1);
    *(uint2*)((char*)g_ylo + off) = make_uint2(l0, l1);
}

// ---------------------------------------------------------------------------
extern "C" void kernel_launch(void* const* d_in, const int* in_sizes, int n_in,
                              void* d_out, int out_size) {
    const float* x  = (const float*)d_in[0];
    const float* Wi = (const float*)d_in[1];
    const float* bi = (const float*)d_in[2];
    const float* Wc = (const float*)d_in[3];
    const float* bc = (const float*)d_in[4];
    const float* Wo = (const float*)d_in[5];
    const float* bo = (const float*)d_in[6];
    float* out = (float*)d_out;

    float* uv_ptr;
    __nv_bfloat16 *xhi, *xlo, *yhi, *ylo, *wihi, *wilo, *wohi, *wolo;
    cudaGetSymbolAddress((void**)&uv_ptr, g_uv);
    cudaGetSymbolAddress((void**)&xhi, g_xhi);
    cudaGetSymbolAddress((void**)&xlo, g_xlo);
    cudaGetSymbolAddress((void**)&yhi, g_yhi);
    cudaGetSymbolAddress((void**)&ylo, g_ylo);
    cudaGetSymbolAddress((void**)&wihi, g_wihi);
    cudaGetSymbolAddress((void**)&wilo, g_wilo);
    cudaGetSymbolAddress((void**)&wohi, g_wohi);
    cudaGetSymbolAddress((void**)&wolo, g_wolo);

    cudaFuncSetAttribute(gemm_mma<2 * DDIM, DDIM>,
                         cudaFuncAttributeMaxDynamicSharedMemorySize, SMEMSZ);
    cudaFuncSetAttribute(gemm_mma<DDIM, DDIM>,
                         cudaFuncAttributeMaxDynamicSharedMemorySize, SMEMSZ);

    cvt_kernel<<<(MROWS * DDIM) / 1024, 256>>>(x, xhi, xlo);
    cvt_kernel<<<(2 * DDIM * DDIM) / 1024, 256>>>(Wi, wihi, wilo);
    cvt_kernel<<<(DDIM * DDIM) / 1024, 256>>>(Wo, wohi, wolo);

    {   // GEMM1: uv = x @ Wi^T + bi
        dim3 grid(2 * DDIM / BN, MROWS / BM);
        gemm_mma<2 * DDIM, DDIM><<<grid, NTH, SMEMSZ>>>(xhi, xlo, wihi, wilo, bi, uv_ptr);
    }
    {   // conv + silu gate -> y hi/lo
        int total = MROWS * (DDIM / 4);
        conv_gate_kernel<<<total / 256, 256>>>(Wc, bc);
    }
    {   // GEMM2: out = y @ Wo^T + bo
        dim3 grid(DDIM / BN, MROWS / BM);
        gemm_mma<DDIM, DDIM><<<grid, NTH, SMEMSZ>>>(yhi, ylo, wohi, wolo, bo, out);
    }
}

// round 7
// speedup vs baseline: 1.4018x; 1.3800x over previous
#include <cuda_runtime.h>
#include <cuda_fp16.h>
#include <cstdint>

// ============================================================================
// MambaBlock, fp16 asymmetric 2-product HMMA (A = hi+lo fp16, B = fp16 round).
//   uv = x@Wi^T+bi ; y = silu(dwconv3(v))*u ; out = y@Wo^T+bo
// D = Ahi*B + Alo*B : only B's fp16 rounding (~2.8e-4 RMS) contributes error.
// ============================================================================

#define MROWS 16384
#define DDIM  1024
#define LSEQ  4096

#define BM 128
#define BN 128
#define BK 32
#define SP 40                    // SMEM row stride in fp16 (32 + 8 pad)
#define NTH 256

#define A_HI 0
#define A_LO (BM * SP * 2)       // 10240
#define B_OF (2 * BM * SP * 2)   // 20480
#define STAGE_BYTES (3 * BM * SP * 2)   // 30720
#define SMEMSZ (2 * STAGE_BYTES)        // 61440

__device__ float g_uv[(size_t)MROWS * 2 * DDIM];
__device__ __half g_xhi[(size_t)MROWS * DDIM];
__device__ __half g_xlo[(size_t)MROWS * DDIM];
__device__ __half g_yhi[(size_t)MROWS * DDIM];
__device__ __half g_ylo[(size_t)MROWS * DDIM];
__device__ __half g_wi [(size_t)2 * DDIM * DDIM];
__device__ __half g_wo [(size_t)DDIM * DDIM];

__device__ __forceinline__ void mma_f16(float* c, const uint32_t* a,
                                        uint32_t b0, uint32_t b1) {
    asm volatile(
        "mma.sync.aligned.m16n8k16.row.col.f32.f16.f16.f32 "
        "{%0,%1,%2,%3}, {%4,%5,%6,%7}, {%8,%9}, {%0,%1,%2,%3};"
        : "+f"(c[0]), "+f"(c[1]), "+f"(c[2]), "+f"(c[3])
        : "r"(a[0]), "r"(a[1]), "r"(a[2]), "r"(a[3]), "r"(b0), "r"(b1));
}

#define LDSM4(r0, r1, r2, r3, addr)                                        \
    asm volatile("ldmatrix.sync.aligned.m8n8.x4.shared.b16 {%0,%1,%2,%3}, [%4];" \
                 : "=r"(r0), "=r"(r1), "=r"(r2), "=r"(r3) : "r"(addr))

#define CPA16(dst, src) \
    asm volatile("cp.async.cg.shared.global [%0], [%1], 16;" :: "r"(dst), "l"(src))
#define CP_COMMIT() asm volatile("cp.async.commit_group;" ::: "memory")
#define CP_WAIT1()  asm volatile("cp.async.wait_group 1;" ::: "memory")
#define CP_WAIT0()  asm volatile("cp.async.wait_group 0;" ::: "memory")

// fp32x4 -> fp16 hi (2 words) + fp16 lo residual (2 words)
__device__ __forceinline__ void cvt_hilo4(float4 v, uint32_t& h0, uint32_t& h1,
                                          uint32_t& l0, uint32_t& l1) {
    __half2 H0 = __floats2half2_rn(v.x, v.y);
    __half2 H1 = __floats2half2_rn(v.z, v.w);
    float r0 = v.x - __low2float(H0);
    float r1 = v.y - __high2float(H0);
    float r2 = v.z - __low2float(H1);
    float r3 = v.w - __high2float(H1);
    __half2 L0 = __floats2half2_rn(r0, r1);
    __half2 L1 = __floats2half2_rn(r2, r3);
    h0 = *reinterpret_cast<uint32_t*>(&H0);
    h1 = *reinterpret_cast<uint32_t*>(&H1);
    l0 = *reinterpret_cast<uint32_t*>(&L0);
    l1 = *reinterpret_cast<uint32_t*>(&L1);
}

// split fp32 -> fp16 hi/lo
__global__ __launch_bounds__(256)
void cvt_split_kernel(const float* __restrict__ src, __half* __restrict__ hi,
                      __half* __restrict__ lo) {
    size_t i4 = ((size_t)blockIdx.x * 256 + threadIdx.x) * 4;
    float4 v = *(const float4*)(src + i4);
    uint32_t h0, h1, l0, l1;
    cvt_hilo4(v, h0, h1, l0, l1);
    *(uint2*)((char*)hi + i4 * 2) = make_uint2(h0, h1);
    *(uint2*)((char*)lo + i4 * 2) = make_uint2(l0, l1);
}

// round fp32 -> fp16
__global__ __launch_bounds__(256)
void cvt_round_kernel(const float* __restrict__ src, __half* __restrict__ dst) {
    size_t i4 = ((size_t)blockIdx.x * 256 + threadIdx.x) * 4;
    float4 v = *(const float4*)(src + i4);
    __half2 H0 = __floats2half2_rn(v.x, v.y);
    __half2 H1 = __floats2half2_rn(v.z, v.w);
    *(uint2*)((char*)dst + i4 * 2) =
        make_uint2(*reinterpret_cast<uint32_t*>(&H0), *reinterpret_cast<uint32_t*>(&H1));
}

// ---------------------------------------------------------------------------
// C[M,N] = (Ahi+Alo)[M,K] @ B[N,K]^T + bias
// ---------------------------------------------------------------------------
template <int N, int K>
__global__ __launch_bounds__(NTH, 2)
void gemm_mma(const __half* __restrict__ Ahi, const __half* __restrict__ Alo,
              const __half* __restrict__ B,
              const float* __restrict__ bias, float* __restrict__ C) {
    extern __shared__ __align__(16) char sm[];
    const uint32_t smb = (uint32_t)__cvta_generic_to_shared(sm);
    const int tid  = threadIdx.x;
    const int lane = tid & 31;
    const int wid  = tid >> 5;
    const int wm   = wid & 3;
    const int wn   = wid >> 2;
    const int qr   = lane >> 2;
    const int qc   = (lane & 3) * 2;
    const int row0 = blockIdx.y * BM;
    const int col0 = blockIdx.x * BN;

    const int m8 = lane >> 3;
    const int rr = lane & 7;
    const uint32_t aLane = (uint32_t)(((wm * 32 + (m8 & 1) * 8 + rr) * SP + (m8 >> 1) * 8) * 2);
    const uint32_t bLane = (uint32_t)(((wn * 64 + (m8 >> 1) * 8 + rr) * SP + (m8 & 1) * 8) * 2);

    const int l_r0 = tid >> 2;       // rows 0..63, +64
    const int l_c  = (tid & 3) * 16;

    float acc[2][8][4];
#pragma unroll
    for (int i = 0; i < 2; i++)
#pragma unroll
        for (int j = 0; j < 8; j++)
#pragma unroll
            for (int k = 0; k < 4; k++) acc[i][j][k] = 0.f;

    const char* pAh = (const char*)(Ahi + (size_t)row0 * K);
    const char* pAl = (const char*)(Alo + (size_t)row0 * K);
    const char* pB  = (const char*)(B   + (size_t)col0 * K);

#define LOAD_STAGE(stageOff, kt) do {                                          \
    const uint32_t so_ = smb + (stageOff);                                     \
    const size_t kb_ = (size_t)(kt) * 2;                                       \
    _Pragma("unroll")                                                          \
    for (int rep = 0; rep < 2; rep++) {                                        \
        int r = l_r0 + rep * 64;                                               \
        uint32_t d = so_ + (uint32_t)(r * (SP * 2) + l_c);                     \
        size_t g = (size_t)r * (K * 2) + kb_ + l_c;                            \
        CPA16(d + A_HI, pAh + g);                                              \
        CPA16(d + A_LO, pAl + g);                                              \
        CPA16(d + B_OF, pB  + g);                                              \
    }                                                                          \
} while (0)

    LOAD_STAGE(0, 0);
    CP_COMMIT();

    constexpr int NCH = K / BK;
#pragma unroll 1
    for (int ck = 0; ck < NCH; ck++) {
        if (ck + 1 < NCH) {
            LOAD_STAGE((uint32_t)(((ck + 1) & 1) * STAGE_BYTES), (ck + 1) * BK);
            CP_COMMIT();
            CP_WAIT1();
        } else {
            CP_WAIT0();
        }
        __syncthreads();

        const uint32_t sto = smb + (uint32_t)((ck & 1) * STAGE_BYTES);
#pragma unroll
        for (int kb = 0; kb < BK; kb += 16) {
            uint32_t ah[2][4], al[2][4], bb[4][4];
#pragma unroll
            for (int mt = 0; mt < 2; mt++) {
                uint32_t ao = sto + aLane + (uint32_t)((mt * 16 * SP + kb) * 2);
                LDSM4(ah[mt][0], ah[mt][1], ah[mt][2], ah[mt][3], ao + A_HI);
                LDSM4(al[mt][0], al[mt][1], al[mt][2], al[mt][3], ao + A_LO);
            }
#pragma unroll
            for (int ntp = 0; ntp < 4; ntp++) {
                uint32_t bo = sto + bLane + (uint32_t)((ntp * 16 * SP + kb) * 2);
                LDSM4(bb[ntp][0], bb[ntp][1], bb[ntp][2], bb[ntp][3], bo + B_OF);
            }
            // pass 1: Ahi * B   (16 independent accumulators)
#pragma unroll
            for (int mt = 0; mt < 2; mt++)
#pragma unroll
                for (int ntp = 0; ntp < 4; ntp++) {
                    mma_f16(acc[mt][2 * ntp],     ah[mt], bb[ntp][0], bb[ntp][1]);
                    mma_f16(acc[mt][2 * ntp + 1], ah[mt], bb[ntp][2], bb[ntp][3]);
                }
            // pass 2: Alo * B
#pragma unroll
            for (int mt = 0; mt < 2; mt++)
#pragma unroll
                for (int ntp = 0; ntp < 4; ntp++) {
                    mma_f16(acc[mt][2 * ntp],     al[mt], bb[ntp][0], bb[ntp][1]);
                    mma_f16(acc[mt][2 * ntp + 1], al[mt], bb[ntp][2], bb[ntp][3]);
                }
        }
        __syncthreads();
    }
#undef LOAD_STAGE

    // epilogue: bias + store
#pragma unroll
    for (int mt = 0; mt < 2; mt++) {
        int row = row0 + wm * 32 + mt * 16 + qr;
#pragma unroll
        for (int nt = 0; nt < 8; nt++) {
            int col = col0 + wn * 64 + nt * 8 + qc;
            float b0 = __ldg(&bias[col]);
            float b1 = __ldg(&bias[col + 1]);
            float2 o0 = make_float2(acc[mt][nt][0] + b0, acc[mt][nt][1] + b1);
            float2 o1 = make_float2(acc[mt][nt][2] + b0, acc[mt][nt][3] + b1);
            *(float2*)(C + (size_t)row * N + col) = o0;
            *(float2*)(C + (size_t)(row + 8) * N + col) = o1;
        }
    }
}

// ---------------------------------------------------------------------------
// depthwise conv3 + silu gate; emits y as fp16 hi/lo
// ---------------------------------------------------------------------------
__global__ __launch_bounds__(256)
void conv_gate_kernel(const float* __restrict__ Wc, const float* __restrict__ bc) {
    int idx = blockIdx.x * blockDim.x + threadIdx.x;
    int m = idx >> 8;
    int d = (idx & 255) << 2;
    int l = m & (LSEQ - 1);

    const float* urow = g_uv + (size_t)m * (2 * DDIM);
    const float* vrow = urow + DDIM;

    float4 vc = *(const float4*)(vrow + d);
    float4 vp = make_float4(0.f, 0.f, 0.f, 0.f);
    float4 vn = make_float4(0.f, 0.f, 0.f, 0.f);
    if (l > 0)        vp = *(const float4*)(vrow - 2 * DDIM + d);
    if (l < LSEQ - 1) vn = *(const float4*)(vrow + 2 * DDIM + d);
    float4 uu = *(const float4*)(urow + d);

    float p[4] = {vp.x, vp.y, vp.z, vp.w};
    float c[4] = {vc.x, vc.y, vc.z, vc.w};
    float n[4] = {vn.x, vn.y, vn.z, vn.w};
    float u[4] = {uu.x, uu.y, uu.z, uu.w};
    float o[4];
#pragma unroll
    for (int j = 0; j < 4; j++) {
        int dd = d + j;
        float t = fmaf(p[j], Wc[dd * 3 + 0],
                  fmaf(c[j], Wc[dd * 3 + 1],
                  fmaf(n[j], Wc[dd * 3 + 2], bc[dd])));
        float s = 1.f / (1.f + __expf(-t));
        o[j] = t * s * u[j];
    }
    uint32_t h0, h1, l0, l1;
    cvt_hilo4(make_float4(o[0], o[1], o[2], o[3]), h0, h1, l0, l1);
    size_t off = ((size_t)m * DDIM + d) * 2;
    *(uint2*)((char*)g_yhi + off) = make_uint2(h0, h1);
    *(uint2*)((char*)g_ylo + off) = make_uint2(l0, l1);
}

// ---------------------------------------------------------------------------
extern "C" void kernel_launch(void* const* d_in, const int* in_sizes, int n_in,
                              void* d_out, int out_size) {
    const float* x  = (const float*)d_in[0];
    const float* Wi = (const float*)d_in[1];
    const float* bi = (const float*)d_in[2];
    const float* Wc = (const float*)d_in[3];
    const float* bc = (const float*)d_in[4];
    const float* Wo = (const float*)d_in[5];
    const float* bo = (const float*)d_in[6];
    float* out = (float*)d_out;

    float* uv_ptr;
    __half *xhi, *xlo, *yhi, *ylo, *wi, *wo;
    cudaGetSymbolAddress((void**)&uv_ptr, g_uv);
    cudaGetSymbolAddress((void**)&xhi, g_xhi);
    cudaGetSymbolAddress((void**)&xlo, g_xlo);
    cudaGetSymbolAddress((void**)&yhi, g_yhi);
    cudaGetSymbolAddress((void**)&ylo, g_ylo);
    cudaGetSymbolAddress((void**)&wi,  g_wi);
    cudaGetSymbolAddress((void**)&wo,  g_wo);

    cudaFuncSetAttribute(gemm_mma<2 * DDIM, DDIM>,
                         cudaFuncAttributeMaxDynamicSharedMemorySize, SMEMSZ);
    cudaFuncSetAttribute(gemm_mma<DDIM, DDIM>,
                         cudaFuncAttributeMaxDynamicSharedMemorySize, SMEMSZ);

    // pre-convert: x -> fp16 hi/lo split; Wi, Wo -> fp16 round
    cvt_split_kernel<<<(MROWS * DDIM) / 1024, 256>>>(x, xhi, xlo);
    cvt_round_kernel<<<(2 * DDIM * DDIM) / 1024, 256>>>(Wi, wi);
    cvt_round_kernel<<<(DDIM * DDIM) / 1024, 256>>>(Wo, wo);

    {   // GEMM1: uv = x @ Wi^T + bi
        dim3 grid(2 * DDIM / BN, MROWS / BM);
        gemm_mma<2 * DDIM, DDIM><<<grid, NTH, SMEMSZ>>>(xhi, xlo, wi, bi, uv_ptr);
    }
    {   // conv + silu gate -> y hi/lo
        int total = MROWS * (DDIM / 4);
        conv_gate_kernel<<<total / 256, 256>>>(Wc, bc);
    }
    {   // GEMM2: out = y @ Wo^T + bo
        dim3 grid(DDIM / BN, MROWS / BM);
        gemm_mma<DDIM, DDIM><<<grid, NTH, SMEMSZ>>>(yhi, ylo, wo, bo, out);
    }
}